// round 6
// baseline (speedup 1.0000x reference)
#include <cuda_runtime.h>
#include <cstdint>

// ---------------------------------------------------------------------------
// ParticleExplorer — time-parallel, two-kernel pipeline.
// Per step: E <- E * Rz(pa) * Ry(na);  x <- x + sp * E.col0
// N = 1024 = 32 chunks x 32 steps. Warp = particle, lane = chunk.
//   K1: chunk transform (P,d) from identity; warp shfl-scan (affine compose);
//       glue with (E0,x0); Gram-Schmidt; store 12-float chunk-start state
//       to g_S (coalesced: index p*32+lane). Folds in speeds/pa/na copies,
//       states=0, and ts.
//   K2: load chunk-start state, replay 32 steps, emit X (float4).
// Output: ts[N] | X[B][N][3] | states[B][N]=0 | speeds | pa | na
// ---------------------------------------------------------------------------

#define LCH 32
#define WPB 8
#define THREADS (WPB * 32)
#define MAXP 8192
#define MAXG (MAXP * 32)

__device__ float g_S[12][MAXG];   // chunk-start state: frame(9) + pos(3)

__device__ __forceinline__ void frame_step(float pa, float na,
    float& a0, float& a1, float& a2,
    float& b0, float& b1, float& b2,
    float& c0, float& c1, float& c2)
{
    float s1, cc1, s2, cc2;
    __sincosf(pa, &s1, &cc1);
    __sincosf(na, &s2, &cc2);
    float p00 = cc1 * cc2, p10 = s1 * cc2;
    float p02 = cc1 * s2,  p12 = s1 * s2;

    float na0 = fmaf(p00, a0, fmaf(p10, b0, -s2 * c0));
    float na1 = fmaf(p00, a1, fmaf(p10, b1, -s2 * c1));
    float na2 = fmaf(p00, a2, fmaf(p10, b2, -s2 * c2));
    float nb0 = fmaf(cc1, b0, -s1 * a0);
    float nb1 = fmaf(cc1, b1, -s1 * a1);
    float nb2 = fmaf(cc1, b2, -s1 * a2);
    float nc0 = fmaf(p02, a0, fmaf(p12, b0, cc2 * c0));
    float nc1 = fmaf(p02, a1, fmaf(p12, b1, cc2 * c1));
    float nc2 = fmaf(p02, a2, fmaf(p12, b2, cc2 * c2));
    a0 = na0; a1 = na1; a2 = na2;
    b0 = nb0; b1 = nb1; b2 = nb2;
    c0 = nc0; c1 = nc1; c2 = nc2;
}

// Affine compose: r earlier, q later (coeffs in r's start basis).
__device__ __forceinline__ void compose(const float* __restrict__ r,
                                        const float* __restrict__ q,
                                        float* __restrict__ o)
{
    #pragma unroll
    for (int col = 0; col < 3; col++) {
        float q0 = q[col*3+0], q1 = q[col*3+1], q2 = q[col*3+2];
        o[col*3+0] = fmaf(q0, r[0], fmaf(q1, r[3], q2 * r[6]));
        o[col*3+1] = fmaf(q0, r[1], fmaf(q1, r[4], q2 * r[7]));
        o[col*3+2] = fmaf(q0, r[2], fmaf(q1, r[5], q2 * r[8]));
    }
    float d0 = q[9], d1 = q[10], d2 = q[11];
    o[9]  = fmaf(d0, r[0], fmaf(d1, r[3], fmaf(d2, r[6], r[9])));
    o[10] = fmaf(d0, r[1], fmaf(d1, r[4], fmaf(d2, r[7], r[10])));
    o[11] = fmaf(d0, r[2], fmaf(d1, r[5], fmaf(d2, r[8], r[11])));
}

// ---- K1: chunk transforms + scan + glue; folds in aux outputs --------------
__global__ void __launch_bounds__(THREADS)
scan_kernel(const float* __restrict__ x0, const float* __restrict__ e0i,
            const float* __restrict__ e1i, const float* __restrict__ e2i,
            const float* __restrict__ spd, const float* __restrict__ pan,
            const float* __restrict__ nanp,
            float* __restrict__ ts, float* __restrict__ states,
            float* __restrict__ spo, float* __restrict__ pao,
            float* __restrict__ nao,
            const int* __restrict__ dtp, int B, int N)
{
    const int tid  = threadIdx.x;
    const int lane = tid & 31;
    const int w    = tid >> 5;
    const int p    = blockIdx.x * WPB + w;
    const int gtid = blockIdx.x * THREADS + tid;

    if (gtid < N) {
        float dtf = 1.0f;
        if (dtp) {
            int vdt = dtp[0];
            if (vdt >= 1 && vdt <= 1000000) dtf = (float)vdt;
            else { float f = __int_as_float(vdt); if (f > 0.f && f < 1.0e6f) dtf = f; }
        }
        ts[gtid] = (float)gtid * dtf;
    }
    if (p >= B) return;

    const size_t base = (size_t)p * N + (size_t)lane * LCH;
    const float4* sp4 = (const float4*)(spd  + base);
    const float4* pa4 = (const float4*)(pan  + base);
    const float4* na4 = (const float4*)(nanp + base);
    float4* spo4 = (float4*)(spo    + base);
    float4* pao4 = (float4*)(pao    + base);
    float4* nao4 = (float4*)(nao    + base);
    float4* st4  = (float4*)(states + base);
    const float4 zero4 = make_float4(0.f, 0.f, 0.f, 0.f);

    // Pass 1: chunk transform from identity (+ pass-through writes).
    float a0=1.f,a1=0.f,a2=0.f, b0=0.f,b1=1.f,b2=0.f, c0=0.f,c1=0.f,c2=1.f;
    float d0=0.f,d1=0.f,d2=0.f;
    #pragma unroll 2
    for (int q = 0; q < LCH / 4; q++) {
        float4 sp = sp4[q], pa = pa4[q], na = na4[q];
        spo4[q] = sp; pao4[q] = pa; nao4[q] = na; st4[q] = zero4;
        frame_step(pa.x, na.x, a0,a1,a2,b0,b1,b2,c0,c1,c2);
        d0 = fmaf(sp.x,a0,d0); d1 = fmaf(sp.x,a1,d1); d2 = fmaf(sp.x,a2,d2);
        frame_step(pa.y, na.y, a0,a1,a2,b0,b1,b2,c0,c1,c2);
        d0 = fmaf(sp.y,a0,d0); d1 = fmaf(sp.y,a1,d1); d2 = fmaf(sp.y,a2,d2);
        frame_step(pa.z, na.z, a0,a1,a2,b0,b1,b2,c0,c1,c2);
        d0 = fmaf(sp.z,a0,d0); d1 = fmaf(sp.z,a1,d1); d2 = fmaf(sp.z,a2,d2);
        frame_step(pa.w, na.w, a0,a1,a2,b0,b1,b2,c0,c1,c2);
        d0 = fmaf(sp.w,a0,d0); d1 = fmaf(sp.w,a1,d1); d2 = fmaf(sp.w,a2,d2);
    }

    float v[12] = {a0,a1,a2, b0,b1,b2, c0,c1,c2, d0,d1,d2};

    // Inclusive shfl scan (Hillis-Steele, affine composition).
    #pragma unroll
    for (int off = 1; off <= 16; off <<= 1) {
        float o[12];
        #pragma unroll
        for (int i = 0; i < 12; i++)
            o[i] = __shfl_up_sync(0xffffffffu, v[i], off);
        if (lane >= off) {
            float t[12];
            compose(o, v, t);
            #pragma unroll
            for (int i = 0; i < 12; i++) v[i] = t[i];
        }
    }
    // Exclusive prefix.
    float e[12];
    #pragma unroll
    for (int i = 0; i < 12; i++)
        e[i] = __shfl_up_sync(0xffffffffu, v[i], 1);
    if (lane == 0) {
        e[0]=1.f; e[1]=0.f; e[2]=0.f;
        e[3]=0.f; e[4]=1.f; e[5]=0.f;
        e[6]=0.f; e[7]=0.f; e[8]=1.f;
        e[9]=0.f; e[10]=0.f; e[11]=0.f;
    }

    // Glue with particle initial frame/pos.
    float A0=e0i[p*3+0], A1=e0i[p*3+1], A2=e0i[p*3+2];
    float B0=e1i[p*3+0], B1=e1i[p*3+1], B2=e1i[p*3+2];
    float C0=e2i[p*3+0], C1=e2i[p*3+1], C2=e2i[p*3+2];
    float x =x0 [p*3+0], y =x0 [p*3+1], z =x0 [p*3+2];

    a0 = fmaf(e[0],A0, fmaf(e[1],B0, e[2]*C0));
    a1 = fmaf(e[0],A1, fmaf(e[1],B1, e[2]*C1));
    a2 = fmaf(e[0],A2, fmaf(e[1],B2, e[2]*C2));
    b0 = fmaf(e[3],A0, fmaf(e[4],B0, e[5]*C0));
    b1 = fmaf(e[3],A1, fmaf(e[4],B1, e[5]*C1));
    b2 = fmaf(e[3],A2, fmaf(e[4],B2, e[5]*C2));
    c0 = fmaf(e[6],A0, fmaf(e[7],B0, e[8]*C0));
    c1 = fmaf(e[6],A1, fmaf(e[7],B1, e[8]*C1));
    c2 = fmaf(e[6],A2, fmaf(e[7],B2, e[8]*C2));
    x  = fmaf(e[9],A0, fmaf(e[10],B0, fmaf(e[11],C0, x)));
    y  = fmaf(e[9],A1, fmaf(e[10],B1, fmaf(e[11],C1, y)));
    z  = fmaf(e[9],A2, fmaf(e[10],B2, fmaf(e[11],C2, z)));

    // Gram-Schmidt renorm (kills composition drift).
    float inv = rsqrtf(fmaf(a0,a0, fmaf(a1,a1, a2*a2)));
    a0*=inv; a1*=inv; a2*=inv;
    float dd = fmaf(b0,a0, fmaf(b1,a1, b2*a2));
    b0 = fmaf(-dd,a0,b0); b1 = fmaf(-dd,a1,b1); b2 = fmaf(-dd,a2,b2);
    inv = rsqrtf(fmaf(b0,b0, fmaf(b1,b1, b2*b2)));
    b0*=inv; b1*=inv; b2*=inv;
    c0 = a1*b2 - a2*b1;
    c1 = a2*b0 - a0*b2;
    c2 = a0*b1 - a1*b0;

    const int g = p * 32 + lane;      // coalesced across the warp
    g_S[0][g]=a0; g_S[1][g]=a1; g_S[2][g]=a2;
    g_S[3][g]=b0; g_S[4][g]=b1; g_S[5][g]=b2;
    g_S[6][g]=c0; g_S[7][g]=c1; g_S[8][g]=c2;
    g_S[9][g]=x;  g_S[10][g]=y; g_S[11][g]=z;
}

// ---- K2: replay chunks, emit X ----------------------------------------------
__global__ void __launch_bounds__(256)
emit_kernel(const float* __restrict__ spd, const float* __restrict__ pan,
            const float* __restrict__ nanp, float* __restrict__ X,
            int B, int N)
{
    const int t = blockIdx.x * 256 + threadIdx.x;
    if (t >= B * 32) return;
    const int p    = t >> 5;
    const int lane = t & 31;

    float a0=g_S[0][t], a1=g_S[1][t], a2=g_S[2][t];
    float b0=g_S[3][t], b1=g_S[4][t], b2=g_S[5][t];
    float c0=g_S[6][t], c1=g_S[7][t], c2=g_S[8][t];
    float x =g_S[9][t], y =g_S[10][t], z =g_S[11][t];

    const size_t base = (size_t)p * N + (size_t)lane * LCH;
    const float4* sp4 = (const float4*)(spd  + base);
    const float4* pa4 = (const float4*)(pan  + base);
    const float4* na4 = (const float4*)(nanp + base);
    float4* X4 = (float4*)(X + (size_t)p * 3 * N + (size_t)lane * (3 * LCH));

    #pragma unroll 2
    for (int q = 0; q < LCH / 4; q++) {
        float4 sp = sp4[q], pa = pa4[q], na = na4[q];
        float4 o0, o1, o2;
        frame_step(pa.x, na.x, a0,a1,a2,b0,b1,b2,c0,c1,c2);
        x = fmaf(sp.x,a0,x); y = fmaf(sp.x,a1,y); z = fmaf(sp.x,a2,z);
        o0.x = x; o0.y = y; o0.z = z;
        frame_step(pa.y, na.y, a0,a1,a2,b0,b1,b2,c0,c1,c2);
        x = fmaf(sp.y,a0,x); y = fmaf(sp.y,a1,y); z = fmaf(sp.y,a2,z);
        o0.w = x; o1.x = y; o1.y = z;
        frame_step(pa.z, na.z, a0,a1,a2,b0,b1,b2,c0,c1,c2);
        x = fmaf(sp.z,a0,x); y = fmaf(sp.z,a1,y); z = fmaf(sp.z,a2,z);
        o1.z = x; o1.w = y; o2.x = z;
        frame_step(pa.w, na.w, a0,a1,a2,b0,b1,b2,c0,c1,c2);
        x = fmaf(sp.w,a0,x); y = fmaf(sp.w,a1,y); z = fmaf(sp.w,a2,z);
        o2.y = x; o2.z = y; o2.w = z;

        X4[q*3 + 0] = o0;
        X4[q*3 + 1] = o1;
        X4[q*3 + 2] = o2;
    }
}

// ---------------------------------------------------------------------------
// Fallback (proven round-2 path) for unexpected shapes.
// ---------------------------------------------------------------------------
#define PPB 32
#define TT  32
#define SPITCH 33

__global__ void __launch_bounds__(PPB)
explorer_kernel(const float* __restrict__ x0, const float* __restrict__ e0i,
                const float* __restrict__ e1i, const float* __restrict__ e2i,
                const float* __restrict__ spd, const float* __restrict__ pan,
                const float* __restrict__ nan_, float* __restrict__ X,
                int B, int N)
{
    __shared__ float s_sp[TT][SPITCH];
    __shared__ float s_pa[TT][SPITCH];
    __shared__ float s_na[TT][SPITCH];
    __shared__ float s_X[3 * TT][SPITCH];

    const int lane  = threadIdx.x;
    const int pbase = blockIdx.x * PPB;
    const int p     = pbase + lane;
    const bool act  = (p < B);

    float a0=1.f,a1=0.f,a2=0.f, b0=0.f,b1=1.f,b2=0.f, c0=0.f,c1=0.f,c2=1.f;
    float x=0.f, y=0.f, z=0.f;
    if (act) {
        a0=e0i[p*3+0]; a1=e0i[p*3+1]; a2=e0i[p*3+2];
        b0=e1i[p*3+0]; b1=e1i[p*3+1]; b2=e1i[p*3+2];
        c0=e2i[p*3+0]; c1=e2i[p*3+1]; c2=e2i[p*3+2];
        x =x0 [p*3+0]; y =x0 [p*3+1]; z =x0 [p*3+2];
    }

    for (int t0 = 0; t0 < N; t0 += TT) {
        #pragma unroll
        for (int k = 0; k < PPB; k++) {
            int gp = pbase + k;
            float vs=0.f, vp=0.f, vn=0.f;
            if (gp < B && t0 + lane < N) {
                size_t gidx = (size_t)gp * N + (size_t)t0 + lane;
                vs = spd[gidx]; vp = pan[gidx]; vn = nan_[gidx];
            }
            s_sp[lane][k]=vs; s_pa[lane][k]=vp; s_na[lane][k]=vn;
        }
        __syncthreads();

        if (act) {
            int nt = (N - t0 < TT) ? (N - t0) : TT;
            for (int tt = 0; tt < nt; tt++) {
                frame_step(s_pa[tt][lane], s_na[tt][lane],
                           a0,a1,a2,b0,b1,b2,c0,c1,c2);
                float s = s_sp[tt][lane];
                x = fmaf(s,a0,x); y = fmaf(s,a1,y); z = fmaf(s,a2,z);
                s_X[3*tt+0][lane]=x; s_X[3*tt+1][lane]=y; s_X[3*tt+2][lane]=z;
            }
            float inv = rsqrtf(fmaf(a0,a0, fmaf(a1,a1, a2*a2)));
            a0*=inv; a1*=inv; a2*=inv;
            float d = fmaf(b0,a0, fmaf(b1,a1, b2*a2));
            b0=fmaf(-d,a0,b0); b1=fmaf(-d,a1,b1); b2=fmaf(-d,a2,b2);
            inv = rsqrtf(fmaf(b0,b0, fmaf(b1,b1, b2*b2)));
            b0*=inv; b1*=inv; b2*=inv;
            c0=a1*b2-a2*b1; c1=a2*b0-a0*b2; c2=a0*b1-a1*b0;
        }
        __syncthreads();

        #pragma unroll
        for (int k = 0; k < PPB; k++) {
            int gp = pbase + k;
            if (gp < B) {
                size_t bidx = (size_t)gp*3*N + (size_t)t0*3;
                #pragma unroll
                for (int chn = 0; chn < 3; chn++)
                    if (t0*3 + chn*32 + lane < 3*N)
                        X[bidx + chn*32 + lane] = s_X[chn*32 + lane][k];
            }
        }
    }
}

__global__ void ts_kernel(float* __restrict__ ts, int N, const int* __restrict__ dtp)
{
    int i = blockIdx.x * blockDim.x + threadIdx.x;
    if (i >= N) return;
    float dtf = 1.0f;
    if (dtp != nullptr) {
        int v = dtp[0];
        if (v >= 1 && v <= 1000000) dtf = (float)v;
        else { float f = __int_as_float(v); if (f > 0.0f && f < 1.0e6f) dtf = f; }
    }
    ts[i] = (float)i * dtf;
}

// ---------------------------------------------------------------------------
extern "C" void kernel_launch(void* const* d_in, const int* in_sizes, int n_in,
                              void* d_out, int out_size)
{
    const float* x0   = (const float*)d_in[0];
    const float* e0   = (const float*)d_in[1];
    const float* e1   = (const float*)d_in[2];
    const float* e2   = (const float*)d_in[3];
    const float* spd  = (const float*)d_in[4];
    const float* pan  = (const float*)d_in[5];
    const float* nan_ = (const float*)d_in[6];

    const int B = in_sizes[0] / 3;
    const int N = (int)((long long)in_sizes[4] / B);

    float* out    = (float*)d_out;
    float* ts     = out;
    float* X      = out + N;
    float* states = X + (size_t)3 * B * N;
    float* sp_o   = states + (size_t)B * N;
    float* pa_o   = sp_o   + (size_t)B * N;
    float* na_o   = pa_o   + (size_t)B * N;

    const int* dtp = (n_in > 8) ? (const int*)d_in[8] : nullptr;

    const bool fast = (N == LCH * 32) && (B % WPB == 0) && (B <= MAXP);

    if (fast) {
        scan_kernel<<<B / WPB, THREADS>>>(x0, e0, e1, e2, spd, pan, nan_,
                                          ts, states, sp_o, pa_o, na_o,
                                          dtp, B, N);
        emit_kernel<<<(B * 32 + 255) / 256, 256>>>(spd, pan, nan_, X, B, N);
    } else {
        const size_t bn_bytes = (size_t)B * N * sizeof(float);
        explorer_kernel<<<(B + PPB - 1) / PPB, PPB>>>(x0, e0, e1, e2,
                                                      spd, pan, nan_, X, B, N);
        ts_kernel<<<(N + 255) / 256, 256>>>(ts, N, dtp);
        cudaMemsetAsync(states, 0, bn_bytes, 0);
        cudaMemcpyAsync(sp_o, d_in[4], bn_bytes, cudaMemcpyDeviceToDevice, 0);
        cudaMemcpyAsync(pa_o, d_in[5], bn_bytes, cudaMemcpyDeviceToDevice, 0);
        cudaMemcpyAsync(na_o, d_in[6], bn_bytes, cudaMemcpyDeviceToDevice, 0);
    }

    (void)out_size; (void)n_in;
}

// round 7
// speedup vs baseline: 2.6851x; 2.6851x over previous
#include <cuda_runtime.h>
#include <cstdint>

// ---------------------------------------------------------------------------
// ParticleExplorer — fused time-parallel kernel, warp-private smem staging.
// Per step: E <- E * Rz(pa) * Ry(na);  x <- x + sp * E.col0
// N = 1024 = 32 chunks x 32 steps. Warp = particle, lane = chunk.
//   stage : coalesced float4 input loads -> smem (swizzled), aux outputs
//           (speeds/pa/na copies, states=0) written coalesced from registers
//   pass 1: chunk transform (P,d) from identity (angles from smem)
//   scan  : 5-step shfl scan (affine composition) -> exclusive prefix
//   glue  : compose with (E0,x0), Gram-Schmidt renorm
//   pass 2: replay chunk, X -> skewed smem, coalesced float4 flush
// Output: ts[N] | X[B][N][3] | states[B][N]=0 | speeds | pa | na
// ---------------------------------------------------------------------------

#define LCH 32
#define WPB 4
#define THREADS (WPB * 32)

// smem sizes (floats)
#define SIN_W   (32 * 33)          // one input array per warp, pitch 33
#define SX_W    (32 * 99)          // X staging per warp, per-lane skew 99
#define SMEM_FLOATS (3 * WPB * SIN_W + WPB * SX_W)

__device__ __forceinline__ void frame_step(float pa, float na,
    float& a0, float& a1, float& a2,
    float& b0, float& b1, float& b2,
    float& c0, float& c1, float& c2)
{
    float s1, cc1, s2, cc2;
    __sincosf(pa, &s1, &cc1);
    __sincosf(na, &s2, &cc2);
    float p00 = cc1 * cc2, p10 = s1 * cc2;
    float p02 = cc1 * s2,  p12 = s1 * s2;

    float na0 = fmaf(p00, a0, fmaf(p10, b0, -s2 * c0));
    float na1 = fmaf(p00, a1, fmaf(p10, b1, -s2 * c1));
    float na2 = fmaf(p00, a2, fmaf(p10, b2, -s2 * c2));
    float nb0 = fmaf(cc1, b0, -s1 * a0);
    float nb1 = fmaf(cc1, b1, -s1 * a1);
    float nb2 = fmaf(cc1, b2, -s1 * a2);
    float nc0 = fmaf(p02, a0, fmaf(p12, b0, cc2 * c0));
    float nc1 = fmaf(p02, a1, fmaf(p12, b1, cc2 * c1));
    float nc2 = fmaf(p02, a2, fmaf(p12, b2, cc2 * c2));
    a0 = na0; a1 = na1; a2 = na2;
    b0 = nb0; b1 = nb1; b2 = nb2;
    c0 = nc0; c1 = nc1; c2 = nc2;
}

// Affine compose: r earlier, q later (coeffs in r's start basis).
__device__ __forceinline__ void compose(const float* __restrict__ r,
                                        const float* __restrict__ q,
                                        float* __restrict__ o)
{
    #pragma unroll
    for (int col = 0; col < 3; col++) {
        float q0 = q[col*3+0], q1 = q[col*3+1], q2 = q[col*3+2];
        o[col*3+0] = fmaf(q0, r[0], fmaf(q1, r[3], q2 * r[6]));
        o[col*3+1] = fmaf(q0, r[1], fmaf(q1, r[4], q2 * r[7]));
        o[col*3+2] = fmaf(q0, r[2], fmaf(q1, r[5], q2 * r[8]));
    }
    float d0 = q[9], d1 = q[10], d2 = q[11];
    o[9]  = fmaf(d0, r[0], fmaf(d1, r[3], fmaf(d2, r[6], r[9])));
    o[10] = fmaf(d0, r[1], fmaf(d1, r[4], fmaf(d2, r[7], r[10])));
    o[11] = fmaf(d0, r[2], fmaf(d1, r[5], fmaf(d2, r[8], r[11])));
}

__global__ void __launch_bounds__(THREADS)
fused_kernel(const float* __restrict__ x0, const float* __restrict__ e0i,
             const float* __restrict__ e1i, const float* __restrict__ e2i,
             const float* __restrict__ spd, const float* __restrict__ pan,
             const float* __restrict__ nanp,
             float* __restrict__ ts, float* __restrict__ X,
             float* __restrict__ states, float* __restrict__ spo,
             float* __restrict__ pao, float* __restrict__ nao,
             const int* __restrict__ dtp, int B, int N)
{
    extern __shared__ float sm[];

    const int tid  = threadIdx.x;
    const int lane = tid & 31;
    const int w    = tid >> 5;
    const int p    = blockIdx.x * WPB + w;
    const int gtid = blockIdx.x * THREADS + tid;

    if (gtid < N) {
        float dtf = 1.0f;
        if (dtp) {
            int vdt = dtp[0];
            if (vdt >= 1 && vdt <= 1000000) dtf = (float)vdt;
            else { float f = __int_as_float(vdt); if (f > 0.f && f < 1.0e6f) dtf = f; }
        }
        ts[gtid] = (float)gtid * dtf;
    }
    if (p >= B) return;   // warp-uniform; no block-wide syncs used below

    float* s_sp = sm + (0 * WPB + w) * SIN_W;
    float* s_pa = sm + (1 * WPB + w) * SIN_W;
    float* s_na = sm + (2 * WPB + w) * SIN_W;
    float* s_x  = sm + 3 * WPB * SIN_W + w * SX_W;

    const size_t pb = (size_t)p * N;
    const float4* g_sp = (const float4*)(spd  + pb);
    const float4* g_pa = (const float4*)(pan  + pb);
    const float4* g_na = (const float4*)(nanp + pb);
    float4* o_sp = (float4*)(spo    + pb);
    float4* o_pa = (float4*)(pao    + pb);
    float4* o_na = (float4*)(nao    + pb);
    float4* o_st = (float4*)(states + pb);
    const float4 zero4 = make_float4(0.f, 0.f, 0.f, 0.f);

    // ---- Stage: coalesced loads -> smem swizzle [within r][chunk c] pitch 33.
    // float4 index f covers elements 4f..4f+3: chunk c = f/8, within r = 4*(f%8).
    #pragma unroll
    for (int j = 0; j < 8; j++) {
        int f = j * 32 + lane;
        float4 vs = g_sp[f], vp = g_pa[f], vn = g_na[f];
        o_sp[f] = vs; o_pa[f] = vp; o_na[f] = vn; o_st[f] = zero4;
        int c = f >> 3;
        int r = (lane & 7) << 2;            // == 4*(f%8)
        s_sp[(r+0)*33 + c] = vs.x; s_sp[(r+1)*33 + c] = vs.y;
        s_sp[(r+2)*33 + c] = vs.z; s_sp[(r+3)*33 + c] = vs.w;
        s_pa[(r+0)*33 + c] = vp.x; s_pa[(r+1)*33 + c] = vp.y;
        s_pa[(r+2)*33 + c] = vp.z; s_pa[(r+3)*33 + c] = vp.w;
        s_na[(r+0)*33 + c] = vn.x; s_na[(r+1)*33 + c] = vn.y;
        s_na[(r+2)*33 + c] = vn.z; s_na[(r+3)*33 + c] = vn.w;
    }
    __syncwarp();

    // ---- Pass 1: chunk transform from identity --------------------------------
    float a0=1.f,a1=0.f,a2=0.f, b0=0.f,b1=1.f,b2=0.f, c0=0.f,c1=0.f,c2=1.f;
    float d0=0.f,d1=0.f,d2=0.f;
    #pragma unroll 4
    for (int i = 0; i < LCH; i++) {
        float pa = s_pa[i*33 + lane];
        float na = s_na[i*33 + lane];
        float sp = s_sp[i*33 + lane];
        frame_step(pa, na, a0,a1,a2,b0,b1,b2,c0,c1,c2);
        d0 = fmaf(sp,a0,d0); d1 = fmaf(sp,a1,d1); d2 = fmaf(sp,a2,d2);
    }

    float v[12] = {a0,a1,a2, b0,b1,b2, c0,c1,c2, d0,d1,d2};

    // ---- Warp inclusive scan (Hillis-Steele, affine composition) --------------
    #pragma unroll
    for (int off = 1; off <= 16; off <<= 1) {
        float o[12];
        #pragma unroll
        for (int i = 0; i < 12; i++)
            o[i] = __shfl_up_sync(0xffffffffu, v[i], off);
        if (lane >= off) {
            float t[12];
            compose(o, v, t);
            #pragma unroll
            for (int i = 0; i < 12; i++) v[i] = t[i];
        }
    }
    // Exclusive prefix.
    float e[12];
    #pragma unroll
    for (int i = 0; i < 12; i++)
        e[i] = __shfl_up_sync(0xffffffffu, v[i], 1);
    if (lane == 0) {
        e[0]=1.f; e[1]=0.f; e[2]=0.f;
        e[3]=0.f; e[4]=1.f; e[5]=0.f;
        e[6]=0.f; e[7]=0.f; e[8]=1.f;
        e[9]=0.f; e[10]=0.f; e[11]=0.f;
    }

    // ---- Glue with particle initial frame/pos ----------------------------------
    float A0=e0i[p*3+0], A1=e0i[p*3+1], A2=e0i[p*3+2];
    float B0=e1i[p*3+0], B1=e1i[p*3+1], B2=e1i[p*3+2];
    float C0=e2i[p*3+0], C1=e2i[p*3+1], C2=e2i[p*3+2];
    float x =x0 [p*3+0], y =x0 [p*3+1], z =x0 [p*3+2];

    a0 = fmaf(e[0],A0, fmaf(e[1],B0, e[2]*C0));
    a1 = fmaf(e[0],A1, fmaf(e[1],B1, e[2]*C1));
    a2 = fmaf(e[0],A2, fmaf(e[1],B2, e[2]*C2));
    b0 = fmaf(e[3],A0, fmaf(e[4],B0, e[5]*C0));
    b1 = fmaf(e[3],A1, fmaf(e[4],B1, e[5]*C1));
    b2 = fmaf(e[3],A2, fmaf(e[4],B2, e[5]*C2));
    c0 = fmaf(e[6],A0, fmaf(e[7],B0, e[8]*C0));
    c1 = fmaf(e[6],A1, fmaf(e[7],B1, e[8]*C1));
    c2 = fmaf(e[6],A2, fmaf(e[7],B2, e[8]*C2));
    x  = fmaf(e[9],A0, fmaf(e[10],B0, fmaf(e[11],C0, x)));
    y  = fmaf(e[9],A1, fmaf(e[10],B1, fmaf(e[11],C1, y)));
    z  = fmaf(e[9],A2, fmaf(e[10],B2, fmaf(e[11],C2, z)));

    // Gram-Schmidt renorm (kills composition drift).
    {
        float inv = rsqrtf(fmaf(a0,a0, fmaf(a1,a1, a2*a2)));
        a0*=inv; a1*=inv; a2*=inv;
        float dd = fmaf(b0,a0, fmaf(b1,a1, b2*a2));
        b0 = fmaf(-dd,a0,b0); b1 = fmaf(-dd,a1,b1); b2 = fmaf(-dd,a2,b2);
        inv = rsqrtf(fmaf(b0,b0, fmaf(b1,b1, b2*b2)));
        b0*=inv; b1*=inv; b2*=inv;
        c0 = a1*b2 - a2*b1;
        c1 = a2*b0 - a0*b2;
        c2 = a0*b1 - a1*b0;
    }

    // ---- Pass 2: replay chunk, X -> skewed smem ---------------------------------
    // Lane's 96 logical floats live at phys = lane*99 + s (3*lane skew mod 32).
    #pragma unroll 4
    for (int i = 0; i < LCH; i++) {
        float pa = s_pa[i*33 + lane];
        float na = s_na[i*33 + lane];
        float sp = s_sp[i*33 + lane];
        frame_step(pa, na, a0,a1,a2,b0,b1,b2,c0,c1,c2);
        x = fmaf(sp,a0,x); y = fmaf(sp,a1,y); z = fmaf(sp,a2,z);
        int ph = lane * 99 + i * 3;
        s_x[ph] = x; s_x[ph+1] = y; s_x[ph+2] = z;
    }
    __syncwarp();

    // ---- Flush X: coalesced float4 stores. A float4 (logical) never crosses a
    // 96-float lane region (96 % 4 == 0): owner = L4/24, s4 = L4%24,
    // phys = owner*99 + 4*s4 (contiguous).
    float4* gX = (float4*)(X + (size_t)p * 3 * N);
    #pragma unroll
    for (int j = 0; j < 24; j++) {
        int L4  = j * 32 + lane;
        int own = L4 / 24;
        int ph  = own * 99 + (L4 - own * 24) * 4;
        gX[L4] = make_float4(s_x[ph], s_x[ph+1], s_x[ph+2], s_x[ph+3]);
    }
}

// ---------------------------------------------------------------------------
// Fallback (proven round-2 path) for unexpected shapes.
// ---------------------------------------------------------------------------
#define PPB 32
#define TT  32
#define SPITCH 33

__global__ void __launch_bounds__(PPB)
explorer_kernel(const float* __restrict__ x0, const float* __restrict__ e0i,
                const float* __restrict__ e1i, const float* __restrict__ e2i,
                const float* __restrict__ spd, const float* __restrict__ pan,
                const float* __restrict__ nan_, float* __restrict__ X,
                int B, int N)
{
    __shared__ float s_sp[TT][SPITCH];
    __shared__ float s_pa[TT][SPITCH];
    __shared__ float s_na[TT][SPITCH];
    __shared__ float s_X[3 * TT][SPITCH];

    const int lane  = threadIdx.x;
    const int pbase = blockIdx.x * PPB;
    const int p     = pbase + lane;
    const bool act  = (p < B);

    float a0=1.f,a1=0.f,a2=0.f, b0=0.f,b1=1.f,b2=0.f, c0=0.f,c1=0.f,c2=1.f;
    float x=0.f, y=0.f, z=0.f;
    if (act) {
        a0=e0i[p*3+0]; a1=e0i[p*3+1]; a2=e0i[p*3+2];
        b0=e1i[p*3+0]; b1=e1i[p*3+1]; b2=e1i[p*3+2];
        c0=e2i[p*3+0]; c1=e2i[p*3+1]; c2=e2i[p*3+2];
        x =x0 [p*3+0]; y =x0 [p*3+1]; z =x0 [p*3+2];
    }

    for (int t0 = 0; t0 < N; t0 += TT) {
        #pragma unroll
        for (int k = 0; k < PPB; k++) {
            int gp = pbase + k;
            float vs=0.f, vp=0.f, vn=0.f;
            if (gp < B && t0 + lane < N) {
                size_t gidx = (size_t)gp * N + (size_t)t0 + lane;
                vs = spd[gidx]; vp = pan[gidx]; vn = nan_[gidx];
            }
            s_sp[lane][k]=vs; s_pa[lane][k]=vp; s_na[lane][k]=vn;
        }
        __syncthreads();

        if (act) {
            int nt = (N - t0 < TT) ? (N - t0) : TT;
            for (int tt = 0; tt < nt; tt++) {
                frame_step(s_pa[tt][lane], s_na[tt][lane],
                           a0,a1,a2,b0,b1,b2,c0,c1,c2);
                float s = s_sp[tt][lane];
                x = fmaf(s,a0,x); y = fmaf(s,a1,y); z = fmaf(s,a2,z);
                s_X[3*tt+0][lane]=x; s_X[3*tt+1][lane]=y; s_X[3*tt+2][lane]=z;
            }
            float inv = rsqrtf(fmaf(a0,a0, fmaf(a1,a1, a2*a2)));
            a0*=inv; a1*=inv; a2*=inv;
            float d = fmaf(b0,a0, fmaf(b1,a1, b2*a2));
            b0=fmaf(-d,a0,b0); b1=fmaf(-d,a1,b1); b2=fmaf(-d,a2,b2);
            inv = rsqrtf(fmaf(b0,b0, fmaf(b1,b1, b2*b2)));
            b0*=inv; b1*=inv; b2*=inv;
            c0=a1*b2-a2*b1; c1=a2*b0-a0*b2; c2=a0*b1-a1*b0;
        }
        __syncthreads();

        #pragma unroll
        for (int k = 0; k < PPB; k++) {
            int gp = pbase + k;
            if (gp < B) {
                size_t bidx = (size_t)gp*3*N + (size_t)t0*3;
                #pragma unroll
                for (int chn = 0; chn < 3; chn++)
                    if (t0*3 + chn*32 + lane < 3*N)
                        X[bidx + chn*32 + lane] = s_X[chn*32 + lane][k];
            }
        }
    }
}

__global__ void ts_kernel(float* __restrict__ ts, int N, const int* __restrict__ dtp)
{
    int i = blockIdx.x * blockDim.x + threadIdx.x;
    if (i >= N) return;
    float dtf = 1.0f;
    if (dtp != nullptr) {
        int v = dtp[0];
        if (v >= 1 && v <= 1000000) dtf = (float)v;
        else { float f = __int_as_float(v); if (f > 0.0f && f < 1.0e6f) dtf = f; }
    }
    ts[i] = (float)i * dtf;
}

// ---------------------------------------------------------------------------
extern "C" void kernel_launch(void* const* d_in, const int* in_sizes, int n_in,
                              void* d_out, int out_size)
{
    const float* x0   = (const float*)d_in[0];
    const float* e0   = (const float*)d_in[1];
    const float* e1   = (const float*)d_in[2];
    const float* e2   = (const float*)d_in[3];
    const float* spd  = (const float*)d_in[4];
    const float* pan  = (const float*)d_in[5];
    const float* nan_ = (const float*)d_in[6];

    const int B = in_sizes[0] / 3;
    const int N = (int)((long long)in_sizes[4] / B);

    float* out    = (float*)d_out;
    float* ts     = out;
    float* X      = out + N;
    float* states = X + (size_t)3 * B * N;
    float* sp_o   = states + (size_t)B * N;
    float* pa_o   = sp_o   + (size_t)B * N;
    float* na_o   = pa_o   + (size_t)B * N;

    const int* dtp = (n_in > 8) ? (const int*)d_in[8] : nullptr;

    const size_t smem_bytes = (size_t)SMEM_FLOATS * sizeof(float);  // ~101 KB
    const bool fast = (N == LCH * 32) && (B % WPB == 0);

    if (fast) {
        cudaFuncSetAttribute(fused_kernel,
                             cudaFuncAttributeMaxDynamicSharedMemorySize,
                             (int)smem_bytes);
        fused_kernel<<<B / WPB, THREADS, smem_bytes>>>(
            x0, e0, e1, e2, spd, pan, nan_,
            ts, X, states, sp_o, pa_o, na_o, dtp, B, N);
    } else {
        const size_t bn_bytes = (size_t)B * N * sizeof(float);
        explorer_kernel<<<(B + PPB - 1) / PPB, PPB>>>(x0, e0, e1, e2,
                                                      spd, pan, nan_, X, B, N);
        ts_kernel<<<(N + 255) / 256, 256>>>(ts, N, dtp);
        cudaMemsetAsync(states, 0, bn_bytes, 0);
        cudaMemcpyAsync(sp_o, d_in[4], bn_bytes, cudaMemcpyDeviceToDevice, 0);
        cudaMemcpyAsync(pa_o, d_in[5], bn_bytes, cudaMemcpyDeviceToDevice, 0);
        cudaMemcpyAsync(na_o, d_in[6], bn_bytes, cudaMemcpyDeviceToDevice, 0);
    }

    (void)out_size; (void)n_in;
}

// round 8
// speedup vs baseline: 3.0123x; 1.1219x over previous
#include <cuda_runtime.h>
#include <cstdint>

// ---------------------------------------------------------------------------
// ParticleExplorer — fused time-parallel kernel, L=16 chunks, 2 warps/particle.
// Per step: E <- E * Rz(pa) * Ry(na);  x <- x + sp * E.col0
// N = 1024 = 64 chunks x 16 steps. Block = 8 warps = 4 particles.
// Warp w: particle slot w/2, half h = w&1 (chunks h*32+lane).
//   stage : coalesced float4 loads -> smem (pitch-34 swizzle), aux outputs
//   pass 1: 16-step chunk transform (P,d) from identity
//   scan  : intra-warp shfl scan + cross-half 12-float smem handoff
//   glue  : compose with (E0,x0), Gram-Schmidt renorm
//   pass 2: replay 16 steps, X -> pitch-49 smem, coalesced float4 flush
// Output: ts[N] | X[B][N][3] | states[B][N]=0 | speeds | pa | na
// ---------------------------------------------------------------------------

#define LCH 16
#define NWARP 8
#define THREADS (NWARP * 32)

#define SIN_PITCH 34
#define SIN_W (LCH * SIN_PITCH)          // 544 floats per array per warp
#define SX_PITCH 49
#define SX_W (32 * SX_PITCH)             // 1568 floats per warp
#define GLUE_OFF (NWARP * (3 * SIN_W) + NWARP * SX_W)   // 25600
#define SMEM_FLOATS (GLUE_OFF + 4 * 16)  // + glue area (4 particles x 16)

__device__ __forceinline__ void frame_step(float pa, float na,
    float& a0, float& a1, float& a2,
    float& b0, float& b1, float& b2,
    float& c0, float& c1, float& c2)
{
    float s1, cc1, s2, cc2;
    __sincosf(pa, &s1, &cc1);
    __sincosf(na, &s2, &cc2);
    float p00 = cc1 * cc2, p10 = s1 * cc2;
    float p02 = cc1 * s2,  p12 = s1 * s2;

    float na0 = fmaf(p00, a0, fmaf(p10, b0, -s2 * c0));
    float na1 = fmaf(p00, a1, fmaf(p10, b1, -s2 * c1));
    float na2 = fmaf(p00, a2, fmaf(p10, b2, -s2 * c2));
    float nb0 = fmaf(cc1, b0, -s1 * a0);
    float nb1 = fmaf(cc1, b1, -s1 * a1);
    float nb2 = fmaf(cc1, b2, -s1 * a2);
    float nc0 = fmaf(p02, a0, fmaf(p12, b0, cc2 * c0));
    float nc1 = fmaf(p02, a1, fmaf(p12, b1, cc2 * c1));
    float nc2 = fmaf(p02, a2, fmaf(p12, b2, cc2 * c2));
    a0 = na0; a1 = na1; a2 = na2;
    b0 = nb0; b1 = nb1; b2 = nb2;
    c0 = nc0; c1 = nc1; c2 = nc2;
}

// Affine compose: r earlier, q later (coeffs in r's start basis).
__device__ __forceinline__ void compose(const float* __restrict__ r,
                                        const float* __restrict__ q,
                                        float* __restrict__ o)
{
    #pragma unroll
    for (int col = 0; col < 3; col++) {
        float q0 = q[col*3+0], q1 = q[col*3+1], q2 = q[col*3+2];
        o[col*3+0] = fmaf(q0, r[0], fmaf(q1, r[3], q2 * r[6]));
        o[col*3+1] = fmaf(q0, r[1], fmaf(q1, r[4], q2 * r[7]));
        o[col*3+2] = fmaf(q0, r[2], fmaf(q1, r[5], q2 * r[8]));
    }
    float d0 = q[9], d1 = q[10], d2 = q[11];
    o[9]  = fmaf(d0, r[0], fmaf(d1, r[3], fmaf(d2, r[6], r[9])));
    o[10] = fmaf(d0, r[1], fmaf(d1, r[4], fmaf(d2, r[7], r[10])));
    o[11] = fmaf(d0, r[2], fmaf(d1, r[5], fmaf(d2, r[8], r[11])));
}

__global__ void __launch_bounds__(THREADS)
fused_kernel(const float* __restrict__ x0, const float* __restrict__ e0i,
             const float* __restrict__ e1i, const float* __restrict__ e2i,
             const float* __restrict__ spd, const float* __restrict__ pan,
             const float* __restrict__ nanp,
             float* __restrict__ ts, float* __restrict__ X,
             float* __restrict__ states, float* __restrict__ spo,
             float* __restrict__ pao, float* __restrict__ nao,
             const int* __restrict__ dtp, int B, int N)
{
    extern __shared__ float sm[];

    const int tid  = threadIdx.x;
    const int lane = tid & 31;
    const int w    = tid >> 5;
    const int h    = w & 1;                 // half (0: steps 0..511, 1: 512..1023)
    const int ps   = w >> 1;                // particle slot in block
    const int p    = blockIdx.x * 4 + ps;
    const int gtid = blockIdx.x * THREADS + tid;

    if (gtid < N) {
        float dtf = 1.0f;
        if (dtp) {
            int vdt = dtp[0];
            if (vdt >= 1 && vdt <= 1000000) dtf = (float)vdt;
            else { float f = __int_as_float(vdt); if (f > 0.f && f < 1.0e6f) dtf = f; }
        }
        ts[gtid] = (float)gtid * dtf;
    }
    // No early return: __syncthreads below needs all threads (grid == B/4 exact).

    float* s_sp = sm + w * (3 * SIN_W);
    float* s_pa = s_sp + SIN_W;
    float* s_na = s_sp + 2 * SIN_W;
    float* s_x  = sm + NWARP * (3 * SIN_W) + w * SX_W;
    float* glue = sm + GLUE_OFF + ps * 16;

    const size_t pb = (size_t)p * N + (size_t)h * 512;
    const float4* g_sp = (const float4*)(spd  + pb);
    const float4* g_pa = (const float4*)(pan  + pb);
    const float4* g_na = (const float4*)(nanp + pb);
    float4* o_sp = (float4*)(spo    + pb);
    float4* o_pa = (float4*)(pao    + pb);
    float4* o_na = (float4*)(nao    + pb);
    float4* o_st = (float4*)(states + pb);
    const float4 zero4 = make_float4(0.f, 0.f, 0.f, 0.f);

    // ---- Stage: coalesced loads -> smem [step i][chunk cih], pitch 34.
    // float4 f covers elements e=4f..4f+3: cih = 8j + lane/4, i = 4*(lane%4)+k.
    #pragma unroll
    for (int j = 0; j < 4; j++) {
        int f = j * 32 + lane;
        float4 vs = g_sp[f], vp = g_pa[f], vn = g_na[f];
        o_sp[f] = vs; o_pa[f] = vp; o_na[f] = vn; o_st[f] = zero4;
        int cih = j * 8 + (lane >> 2);
        int i0  = (lane & 3) << 2;
        s_sp[(i0+0)*SIN_PITCH + cih] = vs.x; s_sp[(i0+1)*SIN_PITCH + cih] = vs.y;
        s_sp[(i0+2)*SIN_PITCH + cih] = vs.z; s_sp[(i0+3)*SIN_PITCH + cih] = vs.w;
        s_pa[(i0+0)*SIN_PITCH + cih] = vp.x; s_pa[(i0+1)*SIN_PITCH + cih] = vp.y;
        s_pa[(i0+2)*SIN_PITCH + cih] = vp.z; s_pa[(i0+3)*SIN_PITCH + cih] = vp.w;
        s_na[(i0+0)*SIN_PITCH + cih] = vn.x; s_na[(i0+1)*SIN_PITCH + cih] = vn.y;
        s_na[(i0+2)*SIN_PITCH + cih] = vn.z; s_na[(i0+3)*SIN_PITCH + cih] = vn.w;
    }
    __syncwarp();

    // ---- Pass 1: 16-step chunk transform from identity -------------------------
    float a0=1.f,a1=0.f,a2=0.f, b0=0.f,b1=1.f,b2=0.f, c0=0.f,c1=0.f,c2=1.f;
    float d0=0.f,d1=0.f,d2=0.f;
    #pragma unroll 4
    for (int i = 0; i < LCH; i++) {
        float pa = s_pa[i*SIN_PITCH + lane];
        float na = s_na[i*SIN_PITCH + lane];
        float sp = s_sp[i*SIN_PITCH + lane];
        frame_step(pa, na, a0,a1,a2,b0,b1,b2,c0,c1,c2);
        d0 = fmaf(sp,a0,d0); d1 = fmaf(sp,a1,d1); d2 = fmaf(sp,a2,d2);
    }

    float v[12] = {a0,a1,a2, b0,b1,b2, c0,c1,c2, d0,d1,d2};

    // ---- Intra-warp inclusive scan (affine composition) -----------------------
    #pragma unroll
    for (int off = 1; off <= 16; off <<= 1) {
        float o[12];
        #pragma unroll
        for (int i = 0; i < 12; i++)
            o[i] = __shfl_up_sync(0xffffffffu, v[i], off);
        if (lane >= off) {
            float t[12];
            compose(o, v, t);
            #pragma unroll
            for (int i = 0; i < 12; i++) v[i] = t[i];
        }
    }

    // Half-0 publishes its total (lane 31 inclusive) for half-1.
    if (h == 0 && lane == 31) {
        #pragma unroll
        for (int i = 0; i < 12; i++) glue[i] = v[i];
    }
    __syncthreads();

    // Exclusive prefix within warp.
    float e[12];
    #pragma unroll
    for (int i = 0; i < 12; i++)
        e[i] = __shfl_up_sync(0xffffffffu, v[i], 1);
    if (lane == 0) {
        e[0]=1.f; e[1]=0.f; e[2]=0.f;
        e[3]=0.f; e[4]=1.f; e[5]=0.f;
        e[6]=0.f; e[7]=0.f; e[8]=1.f;
        e[9]=0.f; e[10]=0.f; e[11]=0.f;
    }
    // Half-1: prepend half-0's total.
    if (h == 1) {
        float T0[12];
        #pragma unroll
        for (int i = 0; i < 12; i++) T0[i] = glue[i];
        float t[12];
        compose(T0, e, t);
        #pragma unroll
        for (int i = 0; i < 12; i++) e[i] = t[i];
    }

    // ---- Glue with particle initial frame/pos ----------------------------------
    float A0=e0i[p*3+0], A1=e0i[p*3+1], A2=e0i[p*3+2];
    float B0=e1i[p*3+0], B1=e1i[p*3+1], B2=e1i[p*3+2];
    float C0=e2i[p*3+0], C1=e2i[p*3+1], C2=e2i[p*3+2];
    float x =x0 [p*3+0], y =x0 [p*3+1], z =x0 [p*3+2];

    a0 = fmaf(e[0],A0, fmaf(e[1],B0, e[2]*C0));
    a1 = fmaf(e[0],A1, fmaf(e[1],B1, e[2]*C1));
    a2 = fmaf(e[0],A2, fmaf(e[1],B2, e[2]*C2));
    b0 = fmaf(e[3],A0, fmaf(e[4],B0, e[5]*C0));
    b1 = fmaf(e[3],A1, fmaf(e[4],B1, e[5]*C1));
    b2 = fmaf(e[3],A2, fmaf(e[4],B2, e[5]*C2));
    c0 = fmaf(e[6],A0, fmaf(e[7],B0, e[8]*C0));
    c1 = fmaf(e[6],A1, fmaf(e[7],B1, e[8]*C1));
    c2 = fmaf(e[6],A2, fmaf(e[7],B2, e[8]*C2));
    x  = fmaf(e[9],A0, fmaf(e[10],B0, fmaf(e[11],C0, x)));
    y  = fmaf(e[9],A1, fmaf(e[10],B1, fmaf(e[11],C1, y)));
    z  = fmaf(e[9],A2, fmaf(e[10],B2, fmaf(e[11],C2, z)));

    // Gram-Schmidt renorm (kills composition drift).
    {
        float inv = rsqrtf(fmaf(a0,a0, fmaf(a1,a1, a2*a2)));
        a0*=inv; a1*=inv; a2*=inv;
        float dd = fmaf(b0,a0, fmaf(b1,a1, b2*a2));
        b0 = fmaf(-dd,a0,b0); b1 = fmaf(-dd,a1,b1); b2 = fmaf(-dd,a2,b2);
        inv = rsqrtf(fmaf(b0,b0, fmaf(b1,b1, b2*b2)));
        b0*=inv; b1*=inv; b2*=inv;
        c0 = a1*b2 - a2*b1;
        c1 = a2*b0 - a0*b2;
        c2 = a0*b1 - a1*b0;
    }

    // ---- Pass 2: replay 16 steps, X -> pitch-49 smem ---------------------------
    #pragma unroll 4
    for (int i = 0; i < LCH; i++) {
        float pa = s_pa[i*SIN_PITCH + lane];
        float na = s_na[i*SIN_PITCH + lane];
        float sp = s_sp[i*SIN_PITCH + lane];
        frame_step(pa, na, a0,a1,a2,b0,b1,b2,c0,c1,c2);
        x = fmaf(sp,a0,x); y = fmaf(sp,a1,y); z = fmaf(sp,a2,z);
        int ph = lane * SX_PITCH + i * 3;
        s_x[ph] = x; s_x[ph+1] = y; s_x[ph+2] = z;
    }
    __syncwarp();

    // ---- Flush X: warp's half = 1536 consecutive floats = 384 float4. ---------
    // Logical L4: owner lane = L4/12, s4 = L4%12, phys = owner*49 + 4*s4.
    float4* gX = (float4*)(X + (size_t)p * 3 * N + (size_t)h * 1536);
    #pragma unroll
    for (int j = 0; j < 12; j++) {
        int L4  = j * 32 + lane;
        int own = L4 / 12;
        int ph  = own * SX_PITCH + (L4 - own * 12) * 4;
        gX[L4] = make_float4(s_x[ph], s_x[ph+1], s_x[ph+2], s_x[ph+3]);
    }
}

// ---------------------------------------------------------------------------
// Fallback (proven round-2 path) for unexpected shapes.
// ---------------------------------------------------------------------------
#define PPB 32
#define TT  32
#define SPITCH 33

__global__ void __launch_bounds__(PPB)
explorer_kernel(const float* __restrict__ x0, const float* __restrict__ e0i,
                const float* __restrict__ e1i, const float* __restrict__ e2i,
                const float* __restrict__ spd, const float* __restrict__ pan,
                const float* __restrict__ nan_, float* __restrict__ X,
                int B, int N)
{
    __shared__ float s_sp[TT][SPITCH];
    __shared__ float s_pa[TT][SPITCH];
    __shared__ float s_na[TT][SPITCH];
    __shared__ float s_X[3 * TT][SPITCH];

    const int lane  = threadIdx.x;
    const int pbase = blockIdx.x * PPB;
    const int p     = pbase + lane;
    const bool act  = (p < B);

    float a0=1.f,a1=0.f,a2=0.f, b0=0.f,b1=1.f,b2=0.f, c0=0.f,c1=0.f,c2=1.f;
    float x=0.f, y=0.f, z=0.f;
    if (act) {
        a0=e0i[p*3+0]; a1=e0i[p*3+1]; a2=e0i[p*3+2];
        b0=e1i[p*3+0]; b1=e1i[p*3+1]; b2=e1i[p*3+2];
        c0=e2i[p*3+0]; c1=e2i[p*3+1]; c2=e2i[p*3+2];
        x =x0 [p*3+0]; y =x0 [p*3+1]; z =x0 [p*3+2];
    }

    for (int t0 = 0; t0 < N; t0 += TT) {
        #pragma unroll
        for (int k = 0; k < PPB; k++) {
            int gp = pbase + k;
            float vs=0.f, vp=0.f, vn=0.f;
            if (gp < B && t0 + lane < N) {
                size_t gidx = (size_t)gp * N + (size_t)t0 + lane;
                vs = spd[gidx]; vp = pan[gidx]; vn = nan_[gidx];
            }
            s_sp[lane][k]=vs; s_pa[lane][k]=vp; s_na[lane][k]=vn;
        }
        __syncthreads();

        if (act) {
            int nt = (N - t0 < TT) ? (N - t0) : TT;
            for (int tt = 0; tt < nt; tt++) {
                frame_step(s_pa[tt][lane], s_na[tt][lane],
                           a0,a1,a2,b0,b1,b2,c0,c1,c2);
                float s = s_sp[tt][lane];
                x = fmaf(s,a0,x); y = fmaf(s,a1,y); z = fmaf(s,a2,z);
                s_X[3*tt+0][lane]=x; s_X[3*tt+1][lane]=y; s_X[3*tt+2][lane]=z;
            }
            float inv = rsqrtf(fmaf(a0,a0, fmaf(a1,a1, a2*a2)));
            a0*=inv; a1*=inv; a2*=inv;
            float d = fmaf(b0,a0, fmaf(b1,a1, b2*a2));
            b0=fmaf(-d,a0,b0); b1=fmaf(-d,a1,b1); b2=fmaf(-d,a2,b2);
            inv = rsqrtf(fmaf(b0,b0, fmaf(b1,b1, b2*b2)));
            b0*=inv; b1*=inv; b2*=inv;
            c0=a1*b2-a2*b1; c1=a2*b0-a0*b2; c2=a0*b1-a1*b0;
        }
        __syncthreads();

        #pragma unroll
        for (int k = 0; k < PPB; k++) {
            int gp = pbase + k;
            if (gp < B) {
                size_t bidx = (size_t)gp*3*N + (size_t)t0*3;
                #pragma unroll
                for (int chn = 0; chn < 3; chn++)
                    if (t0*3 + chn*32 + lane < 3*N)
                        X[bidx + chn*32 + lane] = s_X[chn*32 + lane][k];
            }
        }
    }
}

__global__ void ts_kernel(float* __restrict__ ts, int N, const int* __restrict__ dtp)
{
    int i = blockIdx.x * blockDim.x + threadIdx.x;
    if (i >= N) return;
    float dtf = 1.0f;
    if (dtp != nullptr) {
        int v = dtp[0];
        if (v >= 1 && v <= 1000000) dtf = (float)v;
        else { float f = __int_as_float(v); if (f > 0.0f && f < 1.0e6f) dtf = f; }
    }
    ts[i] = (float)i * dtf;
}

// ---------------------------------------------------------------------------
extern "C" void kernel_launch(void* const* d_in, const int* in_sizes, int n_in,
                              void* d_out, int out_size)
{
    const float* x0   = (const float*)d_in[0];
    const float* e0   = (const float*)d_in[1];
    const float* e1   = (const float*)d_in[2];
    const float* e2   = (const float*)d_in[3];
    const float* spd  = (const float*)d_in[4];
    const float* pan  = (const float*)d_in[5];
    const float* nan_ = (const float*)d_in[6];

    const int B = in_sizes[0] / 3;
    const int N = (int)((long long)in_sizes[4] / B);

    float* out    = (float*)d_out;
    float* ts     = out;
    float* X      = out + N;
    float* states = X + (size_t)3 * B * N;
    float* sp_o   = states + (size_t)B * N;
    float* pa_o   = sp_o   + (size_t)B * N;
    float* na_o   = pa_o   + (size_t)B * N;

    const int* dtp = (n_in > 8) ? (const int*)d_in[8] : nullptr;

    const size_t smem_bytes = (size_t)SMEM_FLOATS * sizeof(float);  // ~100 KB
    const bool fast = (N == 1024) && (B % 4 == 0);

    if (fast) {
        cudaFuncSetAttribute(fused_kernel,
                             cudaFuncAttributeMaxDynamicSharedMemorySize,
                             (int)smem_bytes);
        fused_kernel<<<B / 4, THREADS, smem_bytes>>>(
            x0, e0, e1, e2, spd, pan, nan_,
            ts, X, states, sp_o, pa_o, na_o, dtp, B, N);
    } else {
        const size_t bn_bytes = (size_t)B * N * sizeof(float);
        explorer_kernel<<<(B + PPB - 1) / PPB, PPB>>>(x0, e0, e1, e2,
                                                      spd, pan, nan_, X, B, N);
        ts_kernel<<<(N + 255) / 256, 256>>>(ts, N, dtp);
        cudaMemsetAsync(states, 0, bn_bytes, 0);
        cudaMemcpyAsync(sp_o, d_in[4], bn_bytes, cudaMemcpyDeviceToDevice, 0);
        cudaMemcpyAsync(pa_o, d_in[5], bn_bytes, cudaMemcpyDeviceToDevice, 0);
        cudaMemcpyAsync(na_o, d_in[6], bn_bytes, cudaMemcpyDeviceToDevice, 0);
    }

    (void)out_size; (void)n_in;
}